// round 6
// baseline (speedup 1.0000x reference)
#include <cuda_runtime.h>
#include <math.h>
#include <stdint.h>

#define NB 2048

// ---------------- scratch (device globals; no allocation) ----------------
__device__ float g_h2[NB * 3600];           // conv2+pool out (tf32-rounded) [b][50][6][12]
__device__ float g_c [NB * 2];              // routed capsule outputs
__device__ float g_f1[NB * 500];            // fc1 relu out
__device__ uint2 g_w2f[64 * 4 * 64];        // conv2 B frags: [kc][kk][n] tf32 pairs {k,k+4}
__device__ uint4 g_wpa[160 * 32];           // pcaps A frags (tf32, per-lane a0..a3)
__device__ uint2 g_w1p[452 * 4 * 512];      // fc1 B frags: [kc][kk][n] tf32 pairs {k,k+4}
__device__ uint2 g_w1cf[48];                // conv1 B frags: [(kc*4+t)*3+nt] pairs {k,k+4}
__device__ int2  g_koffc[256];              // conv2 im2col offsets {k,k+4}
__device__ int2  g_koffp[640];              // pcaps im2col offsets {k,k+4}
__device__ int2  g_koff1[16];               // conv1 im2col offsets {k,k+4} (invalid -> 2176)

// ---------------- helpers ----------------
__device__ __forceinline__ unsigned f2tf(float f) {
    unsigned u; asm("cvt.rna.tf32.f32 %0, %1;" : "=r"(u) : "f"(f)); return u;
}
__device__ __forceinline__ void mma8(float* d, unsigned a0, unsigned a1, unsigned a2,
                                     unsigned a3, unsigned b0, unsigned b1) {
    asm volatile(
        "mma.sync.aligned.m16n8k8.row.col.f32.tf32.tf32.f32 "
        "{%0,%1,%2,%3},{%4,%5,%6,%7},{%8,%9},{%0,%1,%2,%3};"
        : "+f"(d[0]), "+f"(d[1]), "+f"(d[2]), "+f"(d[3])
        : "r"(a0), "r"(a1), "r"(a2), "r"(a3), "r"(b0), "r"(b1));
}
__device__ __forceinline__ unsigned sptr(const void* p) {
    return (unsigned)__cvta_generic_to_shared(p);
}
#define CP_ASYNC8(dst, src)  asm volatile("cp.async.ca.shared.global [%0], [%1], 8;"  :: "r"(dst), "l"(src))
#define CP_ASYNC16(dst, src) asm volatile("cp.async.cg.shared.global [%0], [%1], 16;" :: "r"(dst), "l"(src))
#define CP_COMMIT            asm volatile("cp.async.commit_group;")
#define CP_WAIT(n)           asm volatile("cp.async.wait_group %0;" :: "n"(n))

// ---------------- prep: weight fragment layouts + im2col offset tables ----------------
__global__ void prep_k(const float* __restrict__ w2, const float* __restrict__ pw,
                       const float* __restrict__ w1, const float* __restrict__ c1w) {
    int gtid = blockIdx.x * blockDim.x + threadIdx.x;
    int stride = gridDim.x * blockDim.x;
    for (int i = gtid; i < 16384; i += stride) {   // conv2 B frags
        int kc = i >> 8, rem = i & 255, kk = rem >> 6, n = rem & 63;
        int k = kc * 8 + kk;
        float v0 = (n < 50 && k     < 500) ? w2[n * 500 + k]     : 0.f;
        float v1 = (n < 50 && k + 4 < 500) ? w2[n * 500 + k + 4] : 0.f;
        g_w2f[i] = make_uint2(f2tf(v0), f2tf(v1));
    }
    for (int i = gtid; i < 5120; i += stride) {    // pcaps A frags
        int kc = i >> 5, lane = i & 31, g = lane >> 2, t = lane & 3;
        int k0 = kc * 8;
        float v0 = (k0 + t     < 1250) ? pw[g * 1250 + k0 + t]           : 0.f;
        float v1 = (k0 + t     < 1250) ? pw[(g + 8) * 1250 + k0 + t]     : 0.f;
        float v2 = (k0 + t + 4 < 1250) ? pw[g * 1250 + k0 + t + 4]       : 0.f;
        float v3 = (k0 + t + 4 < 1250) ? pw[(g + 8) * 1250 + k0 + t + 4] : 0.f;
        g_wpa[i] = make_uint4(f2tf(v0), f2tf(v1), f2tf(v2), f2tf(v3));
    }
    for (int i = gtid; i < 256; i += stride) {     // conv2 offsets
        int k = (i >> 2) * 8 + (i & 3);
        int o0 = (k < 500) ? (k / 25) * 448 + ((k % 25) / 5) * 28 + (k % 5) : 8960;
        int k4 = k + 4;
        int o1 = (k4 < 500) ? (k4 / 25) * 448 + ((k4 % 25) / 5) * 28 + (k4 % 5) : 8960;
        g_koffc[i] = make_int2(o0, o1);
    }
    for (int i = gtid; i < 640; i += stride) {     // pcaps offsets
        int k = (i >> 2) * 8 + (i & 3);
        int o0 = (k < 1250) ? (k / 25) * 160 + ((k % 25) / 5) * 16 + (k % 5) : 8000;
        int k4 = k + 4;
        int o1 = (k4 < 1250) ? (k4 / 25) * 160 + ((k4 % 25) / 5) * 16 + (k4 % 5) : 8000;
        g_koffp[i] = make_int2(o0, o1);
    }
    for (int i = gtid; i < 48; i += stride) {      // conv1 B frags [(kc*4+t)*3+nt]
        int kct = i / 3, nt = i % 3;
        int kc = kct >> 2, t = kct & 3;
        int k = kc * 8 + t;
        // pairs over n = nt*8 + g handled lane-side; here store per (k, n) with n = g varying
        // layout: fragment value depends on lane's g -> must store 8 g values? No:
        // we store per (kc,t,nt) is insufficient. This slot is filled below instead.
        (void)kct; (void)nt; (void)kc; (void)t; (void)k;
    }
    for (int i = gtid; i < 384; i += stride) {     // conv1 B frags full: [(kc*4+t)*3+nt][g]
        int g8 = i & 7, idx = i >> 3;              // idx in [0,48)
        int kct = idx / 3, nt = idx % 3;
        int kc = kct >> 2, t = kct & 3;
        int k = kc * 8 + t;
        int n = nt * 8 + g8;
        float v0 = (n < 20 && k     < 25) ? c1w[n * 25 + k]     : 0.f;
        float v1 = (n < 20 && k + 4 < 25) ? c1w[n * 25 + k + 4] : 0.f;
        // store at [idx*8 + g8] in a flat region: reuse g_w1cf as uint2[384]? It is 48.
        // Use g_w1cf only if i<48*8 -> need separate array; see g_w1cfx below.
        (void)v0; (void)v1; (void)g8; (void)n;
    }
    for (int i = gtid; i < 16; i += stride) {      // conv1 offsets
        int kc = i >> 2, t = i & 3;
        int k = kc * 8 + t;
        int o0 = (k < 25) ? (k / 5) * 60 + (k % 5) : 2176;
        int k4 = k + 4;
        int o1 = (k4 < 25) ? (k4 / 5) * 60 + (k4 % 5) : 2176;
        g_koff1[i] = make_int2(o0, o1);
    }
    for (int i = gtid; i < 452 * 4 * 512; i += stride) {  // fc1 B frags (K padded to 3616)
        int kc = i >> 11, rem = i & 2047, kk = rem >> 9, n = rem & 511;
        int k = kc * 8 + kk;
        float v0 = (n < 500 && k     < 3602) ? w1[n * 3602 + k]     : 0.f;
        float v1 = (n < 500 && k + 4 < 3602) ? w1[n * 3602 + k + 4] : 0.f;
        g_w1p[i] = make_uint2(f2tf(v0), f2tf(v1));
    }
}

// conv1 B frags with per-lane g: [idx 48][g 8]
__device__ uint2 g_w1cfx[384];
__global__ void prep1_k(const float* __restrict__ c1w) {
    int i = blockIdx.x * blockDim.x + threadIdx.x;
    if (i < 384) {
        int g8 = i & 7, idx = i >> 3;
        int kct = idx / 3, nt = idx % 3;
        int kc = kct >> 2, t = kct & 3;
        int k = kc * 8 + t;
        int n = nt * 8 + g8;
        float v0 = (n < 20 && k     < 25) ? c1w[n * 25 + k]     : 0.f;
        float v1 = (n < 20 && k + 4 < 25) ? c1w[n * 25 + k + 4] : 0.f;
        g_w1cfx[i] = make_uint2(f2tf(v0), f2tf(v1));
    }
}

// ================= fused backbone =================
// dyn smem (108864 B), phase-aliased:
//   [0      .. 37168)  sxt u32[9292]         | post-conv2 alias: sconv f32[14400] (..57600) | sp f32[1152]
//   [37184  .. 70464)  sBf0 uint2[4160]
//   [70464  ..103744)  sBf1 uint2[4160]      | phase0 alias: sx1t u32[4336] | post-conv2 alias: sh2p u32[8096]
//   [103744 ..108864)  skoffp int2[640]
__device__ __forceinline__ float sq1(float s) { return s * fabsf(s) / (1.f + s * s); }

__global__ __launch_bounds__(288, 2) void backbone_k(
    const float* __restrict__ x, const float* __restrict__ c1b,
    const float* __restrict__ c2b, const float* __restrict__ pcb, const float* __restrict__ rw) {
    extern __shared__ __align__(16) unsigned char cs[];
    unsigned* sxt    = (unsigned*)cs;
    uint2*    sBf0   = (uint2*)(cs + 37184);
    uint2*    sBf1   = (uint2*)(cs + 70464);
    float*    sconv  = (float*)cs;
    float*    sp     = (float*)cs;
    unsigned* sx1t   = (unsigned*)(cs + 70464);   // 4336 u32 (2160 data + zero tail)
    unsigned* sh2p   = (unsigned*)(cs + 70464);
    int2*     skoffp = (int2*)(cs + 103744);
    __shared__ float sb1[20];
    __shared__ int2  skoffc[256];
    __shared__ int2  skoff1[16];
    __shared__ uint2 sW1f[384];

    int b = blockIdx.x, tid = threadIdx.x;
    int warp = tid >> 5, lane = tid & 31, g = lane >> 2, t = lane & 3;

    // ---- P0 ----
    for (int i = tid; i < 2160; i += 288) sx1t[i] = f2tf(x[b * 2160 + i]);
    for (int i = 2160 + tid; i < 4336; i += 288) sx1t[i] = 0u;
    if (tid < 20) sb1[tid] = c1b[tid];
    if (tid < 16) skoff1[tid] = g_koff1[tid];
    for (int i = tid; i < 384; i += 288) sW1f[i] = g_w1cfx[i];
    for (int i = tid; i < 256; i += 288) skoffc[i] = g_koffc[i];
    for (int i = tid; i < 640; i += 288) skoffp[i] = g_koffp[i];
    __syncthreads();

    // prefetch conv2 B window 0 (hidden behind conv1)
    for (int i = tid; i < 4096; i += 288) {
        int row = i >> 6, n = i & 63;
        CP_ASYNC8(sptr(&sBf0[row * 65 + n]), &g_w2f[i]);
    }
    CP_COMMIT;

    // ---- conv1 via tf32 mma: M=1792 (pool_pos*4+quad), N=24(20), K=32(25) ----
    // pool = max over 4 consecutive D rows -> 2 warp shuffles
    for (int mt = warp; mt < 112; mt += 9) {
        int m0 = mt * 16 + g;
        int p0 = m0 >> 2, q0 = m0 & 3;
        int base0 = (2 * (p0 / 28) + (q0 >> 1)) * 60 + 2 * (p0 % 28) + (q0 & 1);
        int m1 = m0 + 8;
        int p1 = m1 >> 2, q1 = m1 & 3;
        int base1 = (2 * (p1 / 28) + (q1 >> 1)) * 60 + 2 * (p1 % 28) + (q1 & 1);
        float ac[3][4];
#pragma unroll
        for (int nt = 0; nt < 3; nt++)
#pragma unroll
            for (int q = 0; q < 4; q++) ac[nt][q] = 0.f;
#pragma unroll
        for (int kc = 0; kc < 4; kc++) {
            int2 ko = skoff1[kc * 4 + t];
            unsigned a0 = sx1t[base0 + ko.x];
            unsigned a1 = sx1t[base1 + ko.x];
            unsigned a2 = sx1t[base0 + ko.y];
            unsigned a3 = sx1t[base1 + ko.y];
#pragma unroll
            for (int nt = 0; nt < 3; nt++) {
                uint2 bb = sW1f[((kc * 4 + t) * 3 + nt) * 8 + g];
                mma8(ac[nt], a0, a1, a2, a3, bb.x, bb.y);
            }
        }
        // pool over row-quads via shuffles (g^1, g^2)
#pragma unroll
        for (int nt = 0; nt < 3; nt++)
#pragma unroll
            for (int q = 0; q < 4; q++) {
                float v = ac[nt][q];
                v = fmaxf(v, __shfl_xor_sync(0xffffffffu, v, 4));
                v = fmaxf(v, __shfl_xor_sync(0xffffffffu, v, 8));
                ac[nt][q] = v;
            }
        if ((g & 3) == 0) {
            int grp = g >> 2;   // 0 or 1
            int P = mt * 4 + grp;
#pragma unroll
            for (int nt = 0; nt < 3; nt++) {
                int n = nt * 8 + 2 * t;
                if (n < 20) {
                    sxt[n * 448 + P]     = f2tf(ac[nt][0] + sb1[n]);
                    sxt[n * 448 + P + 2] = f2tf(ac[nt][2] + sb1[n]);
                }
                if (n + 1 < 20) {
                    sxt[(n + 1) * 448 + P]     = f2tf(ac[nt][1] + sb1[n + 1]);
                    sxt[(n + 1) * 448 + P + 2] = f2tf(ac[nt][3] + sb1[n + 1]);
                }
            }
        }
    }
    for (int i = 8960 + tid; i < 9292; i += 288) sxt[i] = 0u;
    __syncthreads();   // conv1 done; sx1t dead

    // prefetch window 1 into sBf1 (sx1t region now dead)
    for (int i = tid; i < 4096; i += 288) {
        int row = i >> 6, n = i & 63;
        CP_ASYNC8(sptr(&sBf1[row * 65 + n]), &g_w2f[4096 + i]);
    }
    CP_COMMIT;
    CP_WAIT(1);
    __syncthreads();   // window 0 visible

    // ---- conv2 via tf32 mma: M=288, N=56(50), K=512(500), double-buffered B ----
    float acc[2][7][4];
#pragma unroll
    for (int s = 0; s < 2; s++)
#pragma unroll
        for (int nt = 0; nt < 7; nt++)
#pragma unroll
            for (int q = 0; q < 4; q++) acc[s][nt][q] = 0.f;

    int pb[2][2];
#pragma unroll
    for (int s = 0; s < 2; s++) {
        int m0 = (warp * 2 + s) * 16 + g;
        pb[s][0] = (m0 / 24) * 28 + (m0 % 24);
        int m1 = m0 + 8;
        pb[s][1] = (m1 / 24) * 28 + (m1 % 24);
    }

    for (int win = 0; win < 4; win++) {
        uint2* sBf = (win & 1) ? sBf1 : sBf0;
#pragma unroll 4
        for (int wk = 0; wk < 16; wk++) {
            int2 ko = skoffc[(win * 16 + wk) * 4 + t];
            unsigned a[2][4];
#pragma unroll
            for (int s = 0; s < 2; s++) {
                a[s][0] = sxt[pb[s][0] + ko.x];
                a[s][1] = sxt[pb[s][1] + ko.x];
                a[s][2] = sxt[pb[s][0] + ko.y];
                a[s][3] = sxt[pb[s][1] + ko.y];
            }
#pragma unroll
            for (int nt = 0; nt < 7; nt++) {
                uint2 bb = sBf[(wk * 4 + t) * 65 + nt * 8 + g];
                mma8(acc[0][nt], a[0][0], a[0][1], a[0][2], a[0][3], bb.x, bb.y);
                mma8(acc[1][nt], a[1][0], a[1][1], a[1][2], a[1][3], bb.x, bb.y);
            }
        }
        __syncthreads();   // done reading this buffer
        if (win < 2) {
            for (int i = tid; i < 4096; i += 288) {
                int row = i >> 6, n = i & 63;
                CP_ASYNC8(sptr(&sBf[row * 65 + n]), &g_w2f[(win + 2) * 4096 + i]);
            }
            CP_COMMIT;
            CP_WAIT(1);
        } else {
            CP_WAIT(0);
        }
        __syncthreads();   // next buffer visible
    }

    // ---- writeout conv2 pre-pool (sconv aliases sxt/sBf0) + zero pcaps buffer ----
#pragma unroll
    for (int s = 0; s < 2; s++) {
        int m0 = (warp * 2 + s) * 16 + g;
#pragma unroll
        for (int nt = 0; nt < 7; nt++) {
            int n0 = nt * 8 + 2 * t;
            if (n0 < 50) {
                sconv[n0 * 288 + m0]     = acc[s][nt][0];
                sconv[n0 * 288 + m0 + 8] = acc[s][nt][2];
            }
            if (n0 + 1 < 50) {
                sconv[(n0 + 1) * 288 + m0]     = acc[s][nt][1];
                sconv[(n0 + 1) * 288 + m0 + 8] = acc[s][nt][3];
            }
        }
    }
    for (int i = tid; i < 8096; i += 288) sh2p[i] = 0u;
    __syncthreads();

    // ---- maxpool + bias -> tf32; padded smem + g_h2 ----
    for (int i = tid; i < 3600; i += 288) {
        int oc = i / 72, rem = i % 72, ph = rem / 12, pw = rem % 12;
        const float* base = &sconv[oc * 288 + ph * 48 + pw * 2];
        float m = fmaxf(fmaxf(base[0], base[1]), fmaxf(base[24], base[25])) + c2b[oc];
        unsigned r = f2tf(m);
        sh2p[oc * 160 + (ph + 2) * 16 + (pw + 2)] = r;
        g_h2[b * 3600 + i] = __uint_as_float(r);
    }
    __syncthreads();

    // ---- pcaps via tf32 mma, 4 independent acc chains + 1-iter prefetch ----
    {
        int nt = warp;
        int p = nt * 8 + g;
        int pbase = (p / 12) * 16 + (p % 12);
        float pa4[4][4];
#pragma unroll
        for (int c = 0; c < 4; c++)
#pragma unroll
            for (int q = 0; q < 4; q++) pa4[c][q] = 0.f;

        uint4 aa = g_wpa[lane];
        int2 ko = skoffp[t];
        unsigned b0 = sh2p[ko.x + pbase];
        unsigned b1 = sh2p[ko.y + pbase];
#pragma unroll 4
        for (int kc = 0; kc < 160; kc++) {
            uint4 aan; int2 kon; unsigned b0n, b1n;
            if (kc < 159) {
                aan = g_wpa[(kc + 1) * 32 + lane];
                kon = skoffp[(kc + 1) * 4 + t];
                b0n = sh2p[kon.x + pbase];
                b1n = sh2p[kon.y + pbase];
            }
            mma8(pa4[kc & 3], aa.x, aa.y, aa.z, aa.w, b0, b1);
            if (kc < 159) { aa = aan; ko = kon; b0 = b0n; b1 = b1n; }
        }
        float pa[4];
#pragma unroll
        for (int q = 0; q < 4; q++)
            pa[q] = (pa4[0][q] + pa4[1][q]) + (pa4[2][q] + pa4[3][q]);

        __syncthreads();   // sconv dead; sp writes begin
        int oc0 = g;
        int n0 = nt * 8 + 2 * t;
        float bsA = pcb[oc0], bsB = pcb[oc0 + 8];
        sp[oc0 * 72 + n0]           = pa[0] + bsA;
        sp[oc0 * 72 + n0 + 1]       = pa[1] + bsA;
        sp[(oc0 + 8) * 72 + n0]     = pa[2] + bsB;
        sp[(oc0 + 8) * 72 + n0 + 1] = pa[3] + bsB;
    }
    __syncthreads();

    // ---- squash + priors + 3-iter routing: warps 0,1 ----
    if (warp < 2) {
        int k = warp;
        float pr[9];
#pragma unroll
        for (int j = 0; j < 9; j++) {
            int r = lane + 32 * j;
            int cw = r / 72, hw = r % 72;
            const float* pbp = sp + cw * 72 + hw;
            float u0 = pbp[0], u1 = pbp[288], u2 = pbp[576], u3 = pbp[864];
            float n2 = u0 * u0 + u1 * u1 + u2 * u2 + u3 * u3;
            float f = sqrtf(n2) / (1.f + n2);
            float4 w4 = *(const float4*)&rw[(k * 288 + r) * 4];
            pr[j] = f * (u0 * w4.x + u1 * w4.y + u2 * w4.z + u3 * w4.w);
        }
        float S = 0.f;
#pragma unroll
        for (int j = 0; j < 9; j++) S += pr[j];
#pragma unroll
        for (int o = 16; o; o >>= 1) S += __shfl_xor_sync(0xffffffffu, S, o);
        float s = S * (1.f / 288.f);
        float v = sq1(s);
        float vsum = v;
#pragma unroll
        for (int it = 0; it < 2; it++) {
            float m = -1e30f;
#pragma unroll
            for (int j = 0; j < 9; j++) m = fmaxf(m, pr[j] * vsum);
#pragma unroll
            for (int o = 16; o; o >>= 1) m = fmaxf(m, __shfl_xor_sync(0xffffffffu, m, o));
            float Z = 0.f, T = 0.f;
#pragma unroll
            for (int j = 0; j < 9; j++) {
                float e = __expf(pr[j] * vsum - m);
                Z += e;
                T = fmaf(e, pr[j], T);
            }
#pragma unroll
            for (int o = 16; o; o >>= 1) {
                Z += __shfl_xor_sync(0xffffffffu, Z, o);
                T += __shfl_xor_sync(0xffffffffu, T, o);
            }
            float s2 = T / Z;
            v = sq1(s2);
            vsum += v;
        }
        if (lane == 0) g_c[b * 2 + k] = v;
    }
}

// ---------------- fc1: M=2048, N=512(500), K=3616(3602); 64x64 tiles, cp.async 3-stage ----------------
__global__ __launch_bounds__(256) void fc1_mma_k(const float* __restrict__ bias) {
    __shared__ __align__(16) unsigned As[3][64 * 36];
    __shared__ __align__(16) uint2 Bsp[3][16 * 65 + 8];
    int m0 = blockIdx.y * 64, n0 = blockIdx.x * 64;
    int tid = threadIdx.x, warp = tid >> 5, lane = tid & 31, g = lane >> 2, t = lane & 3;
    int ws = warp & 3;            // m strip
    int wn = (warp >> 2) * 32;    // n offset
    int mA = tid & 63, kslA = (tid >> 6) * 8;
    int nB = tid & 63, kgB = tid >> 6;

    float acc[4][4];
#pragma unroll
    for (int nt = 0; nt < 4; nt++)
#pragma unroll
        for (int q = 0; q < 4; q++) acc[nt][q] = 0.f;

    auto stage = [&](int kt, int buf) {
        if (kt < 112) {
            const float* src = &g_h2[(m0 + mA) * 3600 + kt * 32 + kslA];
            unsigned d0 = sptr(&As[buf][mA * 36 + kslA]);
            CP_ASYNC16(d0, src);
            CP_ASYNC16(d0 + 16, src + 4);
        } else {
#pragma unroll
            for (int q = 0; q < 8; q++) {
                int k = 3584 + kslA + q;
                unsigned v = 0u;
                if (k < 3600) v = __float_as_uint(g_h2[(m0 + mA) * 3600 + k]);
                else if (k < 3602) v = f2tf(g_c[(m0 + mA) * 2 + (k - 3600)]);
                As[buf][mA * 36 + kslA + q] = v;
            }
        }
#pragma unroll
        for (int kk = 0; kk < 4; kk++)
            CP_ASYNC8(sptr(&Bsp[buf][(kgB * 4 + kk) * 65 + nB]),
                      &g_w1p[(((kt * 4 + kgB) * 4) + kk) * 512 + n0 + nB]);
        CP_COMMIT;
    };

    stage(0, 0);
    stage(1, 1);
    stage(2, 2);

    int buf = 0;
    for (int kt = 0; kt < 113; kt++) {
        if (kt < 111) { CP_WAIT(2); }
        else if (kt == 111) { CP_WAIT(1); }
        else { CP_WAIT(0); }
        __syncthreads();
#pragma unroll
        for (int kc = 0; kc < 4; kc++) {
            unsigned a0 = As[buf][(ws * 16 + g) * 36 + kc * 8 + t];
            unsigned a1 = As[buf][(ws * 16 + g + 8) * 36 + kc * 8 + t];
            unsigned a2 = As[buf][(ws * 16 + g) * 36 + kc * 8 + t + 4];
            unsigned a3 = As[buf][(ws * 16 + g + 8) * 36 + kc * 8 + t + 4];
#pragma unroll
            for (int nt = 0; nt < 4; nt++) {
                uint2 bb = Bsp[buf][(kc * 4 + t) * 65 + wn + nt * 8 + g];
                mma8(acc[nt], a0, a1, a2, a3, bb.x, bb.y);
            }
        }
        __syncthreads();
        if (kt + 3 <= 112) stage(kt + 3, buf);
        buf = (buf == 2) ? 0 : buf + 1;
    }

    int mrow = m0 + ws * 16 + g;
#pragma unroll
    for (int nt = 0; nt < 4; nt++) {
        int n = n0 + wn + nt * 8 + 2 * t;
        if (n < 500) {
            float bv = bias[n];
            g_f1[mrow * 500 + n]       = fmaxf(acc[nt][0] + bv, 0.f);
            g_f1[(mrow + 8) * 500 + n] = fmaxf(acc[nt][2] + bv, 0.f);
        }
        if (n + 1 < 500) {
            float bv = bias[n + 1];
            g_f1[mrow * 500 + n + 1]       = fmaxf(acc[nt][1] + bv, 0.f);
            g_f1[(mrow + 8) * 500 + n + 1] = fmaxf(acc[nt][3] + bv, 0.f);
        }
    }
}

// ---------------- fc2: [f1 | y] @ W2^T + b2, one warp per (b,o) ----------------
__global__ __launch_bounds__(256) void fc2_k(
    const float* __restrict__ y, const float* __restrict__ w2,
    const float* __restrict__ b2, float* __restrict__ out) {
    int warp = (blockIdx.x * blockDim.x + threadIdx.x) >> 5;
    int lane = threadIdx.x & 31;
    int b = warp >> 1, o = warp & 1;
    const float* f1 = g_f1 + b * 500;
    const float* w = w2 + o * 502;
    float s = 0.f;
    for (int j = lane; j < 500; j += 32) s = fmaf(f1[j], w[j], s);
    if (lane == 0) s += w[500] * y[b * 2] + w[501] * y[b * 2 + 1] + b2[o];
#pragma unroll
    for (int off = 16; off; off >>= 1) s += __shfl_xor_sync(0xffffffffu, s, off);
    if (lane == 0) out[b * 2 + o] = s;
}

// ---------------- launch ----------------
extern "C" void kernel_launch(void* const* d_in, const int* in_sizes, int n_in,
                              void* d_out, int out_size) {
    const float* x   = (const float*)d_in[0];
    const float* y   = (const float*)d_in[1];
    const float* c1w = (const float*)d_in[2];
    const float* c1b = (const float*)d_in[3];
    const float* c2w = (const float*)d_in[4];
    const float* c2b = (const float*)d_in[5];
    const float* pw  = (const float*)d_in[6];
    const float* pb  = (const float*)d_in[7];
    const float* rw  = (const float*)d_in[8];
    const float* f1w = (const float*)d_in[9];
    const float* f1b = (const float*)d_in[10];
    const float* f2w = (const float*)d_in[11];
    const float* f2b = (const float*)d_in[12];
    float* out = (float*)d_out;

    const int bb_smem = 108864;
    cudaFuncSetAttribute(backbone_k, cudaFuncAttributeMaxDynamicSharedMemorySize, bb_smem);

    prep_k<<<512, 256>>>(c2w, pw, f1w, c1w);
    prep1_k<<<2, 256>>>(c1w);
    backbone_k<<<NB, 288, bb_smem>>>(x, c1b, c2b, pb, rw);
    dim3 g4(8, 32);
    fc1_mma_k<<<g4, 256>>>(f1b);
    fc2_k<<<NB * 2 / 8, 256>>>(y, f2w, f2b, out);
}

// round 7
// speedup vs baseline: 1.0931x; 1.0931x over previous
#include <cuda_runtime.h>
#include <math.h>
#include <stdint.h>

#define NB 2048

// ---------------- scratch (device globals; no allocation) ----------------
__device__ float g_h2[NB * 3600];           // conv2+pool out (tf32-rounded) [b][50][6][12]
__device__ float g_c [NB * 2];              // routed capsule outputs
__device__ float g_f1[NB * 500];            // fc1 relu out
__device__ float g_fp[4 * NB * 512];        // fc1 split-K partials [s][m][n(512)]
__device__ uint2 g_w2f[64 * 4 * 64];        // conv2 B frags: [kc][kk][n] tf32 pairs {k,k+4}
__device__ uint4 g_wpa[160 * 32];           // pcaps A frags (tf32, per-lane a0..a3)
__device__ uint2 g_w1p[452 * 4 * 512];      // fc1 B frags: [kc][kk][n] tf32 pairs {k,k+4}
__device__ int2  g_koffc[256];              // conv2 im2col offsets {k,k+4}
__device__ int2  g_koffp[640];              // pcaps im2col offsets {k,k+4}

// ---------------- helpers ----------------
__device__ __forceinline__ unsigned f2tf(float f) {
    unsigned u; asm("cvt.rna.tf32.f32 %0, %1;" : "=r"(u) : "f"(f)); return u;
}
__device__ __forceinline__ void mma8(float* d, unsigned a0, unsigned a1, unsigned a2,
                                     unsigned a3, unsigned b0, unsigned b1) {
    asm volatile(
        "mma.sync.aligned.m16n8k8.row.col.f32.tf32.tf32.f32 "
        "{%0,%1,%2,%3},{%4,%5,%6,%7},{%8,%9},{%0,%1,%2,%3};"
        : "+f"(d[0]), "+f"(d[1]), "+f"(d[2]), "+f"(d[3])
        : "r"(a0), "r"(a1), "r"(a2), "r"(a3), "r"(b0), "r"(b1));
}
__device__ __forceinline__ unsigned sptr(const void* p) {
    return (unsigned)__cvta_generic_to_shared(p);
}
#define CP_ASYNC8(dst, src)  asm volatile("cp.async.ca.shared.global [%0], [%1], 8;"  :: "r"(dst), "l"(src))
#define CP_ASYNC16(dst, src) asm volatile("cp.async.cg.shared.global [%0], [%1], 16;" :: "r"(dst), "l"(src))
#define CP_COMMIT            asm volatile("cp.async.commit_group;")
#define CP_WAIT(n)           asm volatile("cp.async.wait_group %0;" :: "n"(n))

// ---------------- prep: weight fragment layouts + im2col offset tables ----------------
__global__ void prep_k(const float* __restrict__ w2, const float* __restrict__ pw,
                       const float* __restrict__ w1) {
    int gtid = blockIdx.x * blockDim.x + threadIdx.x;
    int stride = gridDim.x * blockDim.x;
    for (int i = gtid; i < 16384; i += stride) {   // conv2 B frags
        int kc = i >> 8, rem = i & 255, kk = rem >> 6, n = rem & 63;
        int k = kc * 8 + kk;
        float v0 = (n < 50 && k     < 500) ? w2[n * 500 + k]     : 0.f;
        float v1 = (n < 50 && k + 4 < 500) ? w2[n * 500 + k + 4] : 0.f;
        g_w2f[i] = make_uint2(f2tf(v0), f2tf(v1));
    }
    for (int i = gtid; i < 5120; i += stride) {    // pcaps A frags
        int kc = i >> 5, lane = i & 31, g = lane >> 2, t = lane & 3;
        int k0 = kc * 8;
        float v0 = (k0 + t     < 1250) ? pw[g * 1250 + k0 + t]           : 0.f;
        float v1 = (k0 + t     < 1250) ? pw[(g + 8) * 1250 + k0 + t]     : 0.f;
        float v2 = (k0 + t + 4 < 1250) ? pw[g * 1250 + k0 + t + 4]       : 0.f;
        float v3 = (k0 + t + 4 < 1250) ? pw[(g + 8) * 1250 + k0 + t + 4] : 0.f;
        g_wpa[i] = make_uint4(f2tf(v0), f2tf(v1), f2tf(v2), f2tf(v3));
    }
    for (int i = gtid; i < 256; i += stride) {     // conv2 offsets
        int k = (i >> 2) * 8 + (i & 3);
        int o0 = (k < 500) ? (k / 25) * 448 + ((k % 25) / 5) * 28 + (k % 5) : 8960;
        int k4 = k + 4;
        int o1 = (k4 < 500) ? (k4 / 25) * 448 + ((k4 % 25) / 5) * 28 + (k4 % 5) : 8960;
        g_koffc[i] = make_int2(o0, o1);
    }
    for (int i = gtid; i < 640; i += stride) {     // pcaps offsets
        int k = (i >> 2) * 8 + (i & 3);
        int o0 = (k < 1250) ? (k / 25) * 160 + ((k % 25) / 5) * 16 + (k % 5) : 8000;
        int k4 = k + 4;
        int o1 = (k4 < 1250) ? (k4 / 25) * 160 + ((k4 % 25) / 5) * 16 + (k4 % 5) : 8000;
        g_koffp[i] = make_int2(o0, o1);
    }
    for (int i = gtid; i < 452 * 4 * 512; i += stride) {  // fc1 B frags (K padded to 3616)
        int kc = i >> 11, rem = i & 2047, kk = rem >> 9, n = rem & 511;
        int k = kc * 8 + kk;
        float v0 = (n < 500 && k     < 3602) ? w1[n * 3602 + k]     : 0.f;
        float v1 = (n < 500 && k + 4 < 3602) ? w1[n * 3602 + k + 4] : 0.f;
        g_w1p[i] = make_uint2(f2tf(v0), f2tf(v1));
    }
}

// ================= fused backbone =================
// dyn smem (108864 B), phase-aliased:
//   [0      .. 37168)  sxt u32[9292]         | post-conv2 alias: sconv f32[14400] (..57600) | sp f32[1152]
//   [37184  .. 70464)  sBf0 uint2[4160]
//   [70464  ..103744)  sBf1 uint2[4160]      | phase0 alias: sx1 f32[2160] | post-conv2 alias: sh2p u32[8096]
//   [103744 ..108864)  skoffp int2[640]
__device__ __forceinline__ float sq1(float s) { return s * fabsf(s) / (1.f + s * s); }

__global__ __launch_bounds__(288, 2) void backbone_k(
    const float* __restrict__ x, const float* __restrict__ c1w, const float* __restrict__ c1b,
    const float* __restrict__ c2b, const float* __restrict__ pcb, const float* __restrict__ rw) {
    extern __shared__ __align__(16) unsigned char cs[];
    unsigned* sxt    = (unsigned*)cs;
    uint2*    sBf0   = (uint2*)(cs + 37184);
    uint2*    sBf1   = (uint2*)(cs + 70464);
    float*    sconv  = (float*)cs;
    float*    sp     = (float*)cs;
    float*    sx1    = (float*)(cs + 70464);
    unsigned* sh2p   = (unsigned*)(cs + 70464);
    int2*     skoffp = (int2*)(cs + 103744);
    __shared__ float sw1[500];
    __shared__ float sb1[20];
    __shared__ int2  skoffc[256];

    int b = blockIdx.x, tid = threadIdx.x;
    int warp = tid >> 5, lane = tid & 31, g = lane >> 2, t = lane & 3;

    // ---- P0 ----
    for (int i = tid; i < 2160; i += 288) sx1[i] = x[b * 2160 + i];
    for (int i = tid; i < 500;  i += 288) sw1[i] = c1w[i];
    if (tid < 20) sb1[tid] = c1b[tid];
    for (int i = tid; i < 256; i += 288) skoffc[i] = g_koffc[i];
    for (int i = tid; i < 640; i += 288) skoffp[i] = g_koffp[i];
    __syncthreads();

    // prefetch conv2 B window 0 (hidden behind conv1)
    for (int i = tid; i < 4096; i += 288) {
        int row = i >> 6, n = i & 63;
        CP_ASYNC8(sptr(&sBf0[row * 65 + n]), &g_w2f[i]);
    }
    CP_COMMIT;

    // ---- conv1 + pool (exact fp32): one patch per item serves 4 ocs ----
    for (int i = tid; i < 2240; i += 288) {
        int og = i / 448, pos = i % 448;
        int ph = pos / 28, pw = pos % 28;
        int r0 = ph * 2, c0 = pw * 2;
        float patch[6][6];
#pragma unroll
        for (int pr = 0; pr < 6; pr++) {
            const float2* row = (const float2*)&sx1[(r0 + pr) * 60 + c0];
            float2 p0 = row[0], p1 = row[1], p2 = row[2];
            patch[pr][0] = p0.x; patch[pr][1] = p0.y;
            patch[pr][2] = p1.x; patch[pr][3] = p1.y;
            patch[pr][4] = p2.x; patch[pr][5] = p2.y;
        }
        int oc0 = og * 4;
#pragma unroll
        for (int o = 0; o < 4; o++) {
            const float* wp = &sw1[(oc0 + o) * 25];
            float a00 = 0, a01 = 0, a10 = 0, a11 = 0;
#pragma unroll
            for (int kr = 0; kr < 5; kr++)
#pragma unroll
                for (int kc = 0; kc < 5; kc++) {
                    float wv = wp[kr * 5 + kc];
                    a00 = fmaf(patch[kr][kc],         wv, a00);
                    a01 = fmaf(patch[kr][kc + 1],     wv, a01);
                    a10 = fmaf(patch[kr + 1][kc],     wv, a10);
                    a11 = fmaf(patch[kr + 1][kc + 1], wv, a11);
                }
            sxt[(oc0 + o) * 448 + pos] =
                f2tf(fmaxf(fmaxf(a00, a01), fmaxf(a10, a11)) + sb1[oc0 + o]);
        }
    }
    for (int i = 8960 + tid; i < 9292; i += 288) sxt[i] = 0u;
    __syncthreads();   // conv1 done; sx1 dead

    // prefetch window 1 into sBf1 (sx1 region now dead)
    for (int i = tid; i < 4096; i += 288) {
        int row = i >> 6, n = i & 63;
        CP_ASYNC8(sptr(&sBf1[row * 65 + n]), &g_w2f[4096 + i]);
    }
    CP_COMMIT;
    CP_WAIT(1);
    __syncthreads();   // window 0 visible

    // ---- conv2 via tf32 mma: M=288, N=56(50), K=512(500), double-buffered B ----
    float acc[2][7][4];
#pragma unroll
    for (int s = 0; s < 2; s++)
#pragma unroll
        for (int nt = 0; nt < 7; nt++)
#pragma unroll
            for (int q = 0; q < 4; q++) acc[s][nt][q] = 0.f;

    int pb[2][2];
#pragma unroll
    for (int s = 0; s < 2; s++) {
        int m0 = (warp * 2 + s) * 16 + g;
        pb[s][0] = (m0 / 24) * 28 + (m0 % 24);
        int m1 = m0 + 8;
        pb[s][1] = (m1 / 24) * 28 + (m1 % 24);
    }

    for (int win = 0; win < 4; win++) {
        uint2* sBf = (win & 1) ? sBf1 : sBf0;
#pragma unroll 4
        for (int wk = 0; wk < 16; wk++) {
            int2 ko = skoffc[(win * 16 + wk) * 4 + t];
            unsigned a[2][4];
#pragma unroll
            for (int s = 0; s < 2; s++) {
                a[s][0] = sxt[pb[s][0] + ko.x];
                a[s][1] = sxt[pb[s][1] + ko.x];
                a[s][2] = sxt[pb[s][0] + ko.y];
                a[s][3] = sxt[pb[s][1] + ko.y];
            }
#pragma unroll
            for (int nt = 0; nt < 7; nt++) {
                uint2 bb = sBf[(wk * 4 + t) * 65 + nt * 8 + g];
                mma8(acc[0][nt], a[0][0], a[0][1], a[0][2], a[0][3], bb.x, bb.y);
                mma8(acc[1][nt], a[1][0], a[1][1], a[1][2], a[1][3], bb.x, bb.y);
            }
        }
        __syncthreads();   // done reading this buffer
        if (win < 2) {
            for (int i = tid; i < 4096; i += 288) {
                int row = i >> 6, n = i & 63;
                CP_ASYNC8(sptr(&sBf[row * 65 + n]), &g_w2f[(win + 2) * 4096 + i]);
            }
            CP_COMMIT;
            CP_WAIT(1);
        } else {
            CP_WAIT(0);
        }
        __syncthreads();   // next buffer visible
    }

    // ---- writeout conv2 pre-pool (sconv aliases sxt/sBf0) + zero pcaps buffer ----
#pragma unroll
    for (int s = 0; s < 2; s++) {
        int m0 = (warp * 2 + s) * 16 + g;
#pragma unroll
        for (int nt = 0; nt < 7; nt++) {
            int n0 = nt * 8 + 2 * t;
            if (n0 < 50) {
                sconv[n0 * 288 + m0]     = acc[s][nt][0];
                sconv[n0 * 288 + m0 + 8] = acc[s][nt][2];
            }
            if (n0 + 1 < 50) {
                sconv[(n0 + 1) * 288 + m0]     = acc[s][nt][1];
                sconv[(n0 + 1) * 288 + m0 + 8] = acc[s][nt][3];
            }
        }
    }
    for (int i = tid; i < 8096; i += 288) sh2p[i] = 0u;
    __syncthreads();

    // ---- maxpool + bias -> tf32; padded smem + g_h2 ----
    for (int i = tid; i < 3600; i += 288) {
        int oc = i / 72, rem = i % 72, ph = rem / 12, pw = rem % 12;
        const float* base = &sconv[oc * 288 + ph * 48 + pw * 2];
        float m = fmaxf(fmaxf(base[0], base[1]), fmaxf(base[24], base[25])) + c2b[oc];
        unsigned r = f2tf(m);
        sh2p[oc * 160 + (ph + 2) * 16 + (pw + 2)] = r;
        g_h2[b * 3600 + i] = __uint_as_float(r);
    }
    __syncthreads();

    // ---- pcaps via tf32 mma, 4 independent acc chains + 1-iter prefetch ----
    {
        int nt = warp;
        int p = nt * 8 + g;
        int pbase = (p / 12) * 16 + (p % 12);
        float pa4[4][4];
#pragma unroll
        for (int c = 0; c < 4; c++)
#pragma unroll
            for (int q = 0; q < 4; q++) pa4[c][q] = 0.f;

        uint4 aa = g_wpa[lane];
        int2 ko = skoffp[t];
        unsigned b0 = sh2p[ko.x + pbase];
        unsigned b1 = sh2p[ko.y + pbase];
#pragma unroll 4
        for (int kc = 0; kc < 160; kc++) {
            uint4 aan; int2 kon; unsigned b0n, b1n;
            if (kc < 159) {
                aan = g_wpa[(kc + 1) * 32 + lane];
                kon = skoffp[(kc + 1) * 4 + t];
                b0n = sh2p[kon.x + pbase];
                b1n = sh2p[kon.y + pbase];
            }
            mma8(pa4[kc & 3], aa.x, aa.y, aa.z, aa.w, b0, b1);
            if (kc < 159) { aa = aan; ko = kon; b0 = b0n; b1 = b1n; }
        }
        float pa[4];
#pragma unroll
        for (int q = 0; q < 4; q++)
            pa[q] = (pa4[0][q] + pa4[1][q]) + (pa4[2][q] + pa4[3][q]);

        __syncthreads();   // sconv dead; sp writes begin
        int oc0 = g;
        int n0 = nt * 8 + 2 * t;
        float bsA = pcb[oc0], bsB = pcb[oc0 + 8];
        sp[oc0 * 72 + n0]           = pa[0] + bsA;
        sp[oc0 * 72 + n0 + 1]       = pa[1] + bsA;
        sp[(oc0 + 8) * 72 + n0]     = pa[2] + bsB;
        sp[(oc0 + 8) * 72 + n0 + 1] = pa[3] + bsB;
    }
    __syncthreads();

    // ---- squash + priors + 3-iter routing: warps 0,1 ----
    if (warp < 2) {
        int k = warp;
        float pr[9];
#pragma unroll
        for (int j = 0; j < 9; j++) {
            int r = lane + 32 * j;
            int cw = r / 72, hw = r % 72;
            const float* pbp = sp + cw * 72 + hw;
            float u0 = pbp[0], u1 = pbp[288], u2 = pbp[576], u3 = pbp[864];
            float n2 = u0 * u0 + u1 * u1 + u2 * u2 + u3 * u3;
            float f = sqrtf(n2) / (1.f + n2);
            float4 w4 = *(const float4*)&rw[(k * 288 + r) * 4];
            pr[j] = f * (u0 * w4.x + u1 * w4.y + u2 * w4.z + u3 * w4.w);
        }
        float S = 0.f;
#pragma unroll
        for (int j = 0; j < 9; j++) S += pr[j];
#pragma unroll
        for (int o = 16; o; o >>= 1) S += __shfl_xor_sync(0xffffffffu, S, o);
        float s = S * (1.f / 288.f);
        float v = sq1(s);
        float vsum = v;
#pragma unroll
        for (int it = 0; it < 2; it++) {
            float m = -1e30f;
#pragma unroll
            for (int j = 0; j < 9; j++) m = fmaxf(m, pr[j] * vsum);
#pragma unroll
            for (int o = 16; o; o >>= 1) m = fmaxf(m, __shfl_xor_sync(0xffffffffu, m, o));
            float Z = 0.f, T = 0.f;
#pragma unroll
            for (int j = 0; j < 9; j++) {
                float e = __expf(pr[j] * vsum - m);
                Z += e;
                T = fmaf(e, pr[j], T);
            }
#pragma unroll
            for (int o = 16; o; o >>= 1) {
                Z += __shfl_xor_sync(0xffffffffu, Z, o);
                T += __shfl_xor_sync(0xffffffffu, T, o);
            }
            float s2 = T / Z;
            v = sq1(s2);
            vsum += v;
        }
        if (lane == 0) g_c[b * 2 + k] = v;
    }
}

// ---------------- fc1 split-K: M=2048, N=512(500), K=3616(3602), Ksplit=4 ----------------
// grid (8 n-tiles, 32 m-tiles, 4 k-splits); each CTA does 28-29 k-tiles, writes partials.
__global__ __launch_bounds__(256) void fc1_mma_k() {
    __shared__ __align__(16) unsigned As[3][64 * 36];
    __shared__ __align__(16) uint2 Bsp[3][16 * 65 + 8];
    int m0 = blockIdx.y * 64, n0 = blockIdx.x * 64;
    int ks = blockIdx.z;
    int ktb = (113 * ks) >> 2;           // 0,28,56,84
    int kte = (113 * (ks + 1)) >> 2;     // 28,56,84,113
    int tid = threadIdx.x, warp = tid >> 5, lane = tid & 31, g = lane >> 2, t = lane & 3;
    int ws = warp & 3;            // m strip
    int wn = (warp >> 2) * 32;    // n offset
    int mA = tid & 63, kslA = (tid >> 6) * 8;
    int nB = tid & 63, kgB = tid >> 6;

    float acc[4][4];
#pragma unroll
    for (int nt = 0; nt < 4; nt++)
#pragma unroll
        for (int q = 0; q < 4; q++) acc[nt][q] = 0.f;

    auto stage = [&](int kt, int buf) {
        if (kt < 112) {
            const float* src = &g_h2[(m0 + mA) * 3600 + kt * 32 + kslA];
            unsigned d0 = sptr(&As[buf][mA * 36 + kslA]);
            CP_ASYNC16(d0, src);
            CP_ASYNC16(d0 + 16, src + 4);
        } else {
#pragma unroll
            for (int q = 0; q < 8; q++) {
                int k = 3584 + kslA + q;
                unsigned v = 0u;
                if (k < 3600) v = __float_as_uint(g_h2[(m0 + mA) * 3600 + k]);
                else if (k < 3602) v = f2tf(g_c[(m0 + mA) * 2 + (k - 3600)]);
                As[buf][mA * 36 + kslA + q] = v;
            }
        }
#pragma unroll
        for (int kk = 0; kk < 4; kk++)
            CP_ASYNC8(sptr(&Bsp[buf][(kgB * 4 + kk) * 65 + nB]),
                      &g_w1p[(((kt * 4 + kgB) * 4) + kk) * 512 + n0 + nB]);
        CP_COMMIT;
    };

    stage(ktb,     0);
    stage(ktb + 1, 1);
    stage(ktb + 2, 2);

    int buf = 0;
    for (int kt = ktb; kt < kte; kt++) {
        if (kt < kte - 2) { CP_WAIT(2); }
        else if (kt == kte - 2) { CP_WAIT(1); }
        else { CP_WAIT(0); }
        __syncthreads();
#pragma unroll
        for (int kc = 0; kc < 4; kc++) {
            unsigned a0 = As[buf][(ws * 16 + g) * 36 + kc * 8 + t];
            unsigned a1 = As[buf][(ws * 16 + g + 8) * 36 + kc * 8 + t];
            unsigned a2 = As[buf][(ws * 16 + g) * 36 + kc * 8 + t + 4];
            unsigned a3 = As[buf][(ws * 16 + g + 8) * 36 + kc * 8 + t + 4];
#pragma unroll
            for (int nt = 0; nt < 4; nt++) {
                uint2 bb = Bsp[buf][(kc * 4 + t) * 65 + wn + nt * 8 + g];
                mma8(acc[nt], a0, a1, a2, a3, bb.x, bb.y);
            }
        }
        __syncthreads();
        if (kt + 3 < kte) stage(kt + 3, buf);
        buf = (buf == 2) ? 0 : buf + 1;
    }

    float* dst = &g_fp[(size_t)ks * NB * 512];
    int mrow = m0 + ws * 16 + g;
#pragma unroll
    for (int nt = 0; nt < 4; nt++) {
        int n = n0 + wn + nt * 8 + 2 * t;
        dst[mrow * 512 + n]           = acc[nt][0];
        dst[mrow * 512 + n + 1]       = acc[nt][1];
        dst[(mrow + 8) * 512 + n]     = acc[nt][2];
        dst[(mrow + 8) * 512 + n + 1] = acc[nt][3];
    }
}

// ---------------- fc1 reduce: relu(sum of 4 partials + bias) ----------------
__global__ __launch_bounds__(256) void fc1_red_k(const float* __restrict__ bias) {
    int i = blockIdx.x * 256 + threadIdx.x;
    if (i < NB * 500) {
        int m = i / 500, n = i % 500;
        int o = m * 512 + n;
        float v = (g_fp[o] + g_fp[NB * 512 + o]) +
                  (g_fp[2 * NB * 512 + o] + g_fp[3 * NB * 512 + o]);
        g_f1[i] = fmaxf(v + bias[n], 0.f);
    }
}

// ---------------- fc2: [f1 | y] @ W2^T + b2, one warp per (b,o) ----------------
__global__ __launch_bounds__(256) void fc2_k(
    const float* __restrict__ y, const float* __restrict__ w2,
    const float* __restrict__ b2, float* __restrict__ out) {
    int warp = (blockIdx.x * blockDim.x + threadIdx.x) >> 5;
    int lane = threadIdx.x & 31;
    int b = warp >> 1, o = warp & 1;
    const float* f1 = g_f1 + b * 500;
    const float* w = w2 + o * 502;
    float s = 0.f;
    for (int j = lane; j < 500; j += 32) s = fmaf(f1[j], w[j], s);
    if (lane == 0) s += w[500] * y[b * 2] + w[501] * y[b * 2 + 1] + b2[o];
#pragma unroll
    for (int off = 16; off; off >>= 1) s += __shfl_xor_sync(0xffffffffu, s, off);
    if (lane == 0) out[b * 2 + o] = s;
}

// ---------------- launch ----------------
extern "C" void kernel_launch(void* const* d_in, const int* in_sizes, int n_in,
                              void* d_out, int out_size) {
    const float* x   = (const float*)d_in[0];
    const float* y   = (const float*)d_in[1];
    const float* c1w = (const float*)d_in[2];
    const float* c1b = (const float*)d_in[3];
    const float* c2w = (const float*)d_in[4];
    const float* c2b = (const float*)d_in[5];
    const float* pw  = (const float*)d_in[6];
    const float* pb  = (const float*)d_in[7];
    const float* rw  = (const float*)d_in[8];
    const float* f1w = (const float*)d_in[9];
    const float* f1b = (const float*)d_in[10];
    const float* f2w = (const float*)d_in[11];
    const float* f2b = (const float*)d_in[12];
    float* out = (float*)d_out;

    const int bb_smem = 108864;
    cudaFuncSetAttribute(backbone_k, cudaFuncAttributeMaxDynamicSharedMemorySize, bb_smem);

    prep_k<<<512, 256>>>(c2w, pw, f1w);
    backbone_k<<<NB, 288, bb_smem>>>(x, c1w, c1b, c2b, pb, rw);
    dim3 g4(8, 32, 4);
    fc1_mma_k<<<g4, 256>>>();
    fc1_red_k<<<(NB * 500 + 255) / 256, 256>>>(f1b);
    fc2_k<<<NB * 2 / 8, 256>>>(y, f2w, f2b, out);
}

// round 8
// speedup vs baseline: 1.1196x; 1.0242x over previous
#include <cuda_runtime.h>
#include <math.h>
#include <stdint.h>

#define NB 2048

// ---------------- scratch (device globals; no allocation) ----------------
__device__ float g_h2[NB * 3600];           // conv2+pool out (tf32-rounded) [b][50][6][12]
__device__ float g_c [NB * 2];              // routed capsule outputs
__device__ float g_fp[4 * NB * 512];        // fc1 split-K partials [s][m][n(512)]
__device__ uint2 g_w2f[64 * 4 * 64];        // conv2 B frags: [kc][kk][n] tf32 pairs {k,k+4}
__device__ uint4 g_wpa[160 * 32];           // pcaps A frags (tf32, per-lane a0..a3)
__device__ uint2 g_w1p[452 * 4 * 512];      // fc1 B frags: [kc][kk][n] tf32 pairs {k,k+4}
__device__ int2  g_koffc[256];              // conv2 im2col offsets {k,k+4}
__device__ int2  g_koffp[640];              // pcaps im2col offsets {k,k+4}

// ---------------- helpers ----------------
__device__ __forceinline__ unsigned f2tf(float f) {
    unsigned u; asm("cvt.rna.tf32.f32 %0, %1;" : "=r"(u) : "f"(f)); return u;
}
__device__ __forceinline__ void mma8(float* d, unsigned a0, unsigned a1, unsigned a2,
                                     unsigned a3, unsigned b0, unsigned b1) {
    asm volatile(
        "mma.sync.aligned.m16n8k8.row.col.f32.tf32.tf32.f32 "
        "{%0,%1,%2,%3},{%4,%5,%6,%7},{%8,%9},{%0,%1,%2,%3};"
        : "+f"(d[0]), "+f"(d[1]), "+f"(d[2]), "+f"(d[3])
        : "r"(a0), "r"(a1), "r"(a2), "r"(a3), "r"(b0), "r"(b1));
}
__device__ __forceinline__ unsigned sptr(const void* p) {
    return (unsigned)__cvta_generic_to_shared(p);
}
#define CP_ASYNC8(dst, src)  asm volatile("cp.async.ca.shared.global [%0], [%1], 8;"  :: "r"(dst), "l"(src))
#define CP_ASYNC16(dst, src) asm volatile("cp.async.cg.shared.global [%0], [%1], 16;" :: "r"(dst), "l"(src))
#define CP_COMMIT            asm volatile("cp.async.commit_group;")
#define CP_WAIT(n)           asm volatile("cp.async.wait_group %0;" :: "n"(n))

// ---------------- prep: weight fragment layouts + im2col offset tables ----------------
__global__ void prep_k(const float* __restrict__ w2, const float* __restrict__ pw,
                       const float* __restrict__ w1) {
    int gtid = blockIdx.x * blockDim.x + threadIdx.x;
    int stride = gridDim.x * blockDim.x;
    for (int i = gtid; i < 16384; i += stride) {   // conv2 B frags
        int kc = i >> 8, rem = i & 255, kk = rem >> 6, n = rem & 63;
        int k = kc * 8 + kk;
        float v0 = (n < 50 && k     < 500) ? w2[n * 500 + k]     : 0.f;
        float v1 = (n < 50 && k + 4 < 500) ? w2[n * 500 + k + 4] : 0.f;
        g_w2f[i] = make_uint2(f2tf(v0), f2tf(v1));
    }
    for (int i = gtid; i < 5120; i += stride) {    // pcaps A frags
        int kc = i >> 5, lane = i & 31, g = lane >> 2, t = lane & 3;
        int k0 = kc * 8;
        float v0 = (k0 + t     < 1250) ? pw[g * 1250 + k0 + t]           : 0.f;
        float v1 = (k0 + t     < 1250) ? pw[(g + 8) * 1250 + k0 + t]     : 0.f;
        float v2 = (k0 + t + 4 < 1250) ? pw[g * 1250 + k0 + t + 4]       : 0.f;
        float v3 = (k0 + t + 4 < 1250) ? pw[(g + 8) * 1250 + k0 + t + 4] : 0.f;
        g_wpa[i] = make_uint4(f2tf(v0), f2tf(v1), f2tf(v2), f2tf(v3));
    }
    for (int i = gtid; i < 256; i += stride) {     // conv2 offsets
        int k = (i >> 2) * 8 + (i & 3);
        int o0 = (k < 500) ? (k / 25) * 448 + ((k % 25) / 5) * 28 + (k % 5) : 8960;
        int k4 = k + 4;
        int o1 = (k4 < 500) ? (k4 / 25) * 448 + ((k4 % 25) / 5) * 28 + (k4 % 5) : 8960;
        g_koffc[i] = make_int2(o0, o1);
    }
    for (int i = gtid; i < 640; i += stride) {     // pcaps offsets
        int k = (i >> 2) * 8 + (i & 3);
        int o0 = (k < 1250) ? (k / 25) * 160 + ((k % 25) / 5) * 16 + (k % 5) : 8000;
        int k4 = k + 4;
        int o1 = (k4 < 1250) ? (k4 / 25) * 160 + ((k4 % 25) / 5) * 16 + (k4 % 5) : 8000;
        g_koffp[i] = make_int2(o0, o1);
    }
    for (int i = gtid; i < 452 * 4 * 512; i += stride) {  // fc1 B frags (K padded to 3616)
        int kc = i >> 11, rem = i & 2047, kk = rem >> 9, n = rem & 511;
        int k = kc * 8 + kk;
        float v0 = (n < 500 && k     < 3602) ? w1[n * 3602 + k]     : 0.f;
        float v1 = (n < 500 && k + 4 < 3602) ? w1[n * 3602 + k + 4] : 0.f;
        g_w1p[i] = make_uint2(f2tf(v0), f2tf(v1));
    }
}

// ================= fused backbone =================
// dyn smem (108864 B), phase-aliased:
//   [0      .. 37168)  sxt u32[9292]         | post-conv2 alias: sconv f32[14400] (..57600) | sp f32[1152] @0
//   [8192   .. 49152)  swc uint4[2][1280] (pcaps weight stage; alive only during pcaps mma)
//   [37184  .. 70464)  sBf0 uint2[4160]
//   [70464  ..103744)  sBf1 uint2[4160]      | phase0 alias: sx1 f32[2160] | post-conv2 alias: sh2p u32[8096]
//   [103744 ..108864)  skoffp int2[640]
__device__ __forceinline__ float sq1(float s) { return s * fabsf(s) / (1.f + s * s); }

__global__ __launch_bounds__(288, 2) void backbone_k(
    const float* __restrict__ x, const float* __restrict__ c1w, const float* __restrict__ c1b,
    const float* __restrict__ c2b, const float* __restrict__ pcb, const float* __restrict__ rw) {
    extern __shared__ __align__(16) unsigned char cs[];
    unsigned* sxt    = (unsigned*)cs;
    uint2*    sBf0   = (uint2*)(cs + 37184);
    uint2*    sBf1   = (uint2*)(cs + 70464);
    float*    sconv  = (float*)cs;
    float*    sp     = (float*)cs;
    uint4*    swc    = (uint4*)(cs + 8192);
    float*    sx1    = (float*)(cs + 70464);
    unsigned* sh2p   = (unsigned*)(cs + 70464);
    int2*     skoffp = (int2*)(cs + 103744);
    __shared__ float sw1[500];
    __shared__ float sb1[20];
    __shared__ int2  skoffc[256];

    int b = blockIdx.x, tid = threadIdx.x;
    int warp = tid >> 5, lane = tid & 31, g = lane >> 2, t = lane & 3;

    // ---- P0 ----
    for (int i = tid; i < 2160; i += 288) sx1[i] = x[b * 2160 + i];
    for (int i = tid; i < 500;  i += 288) sw1[i] = c1w[i];
    if (tid < 20) sb1[tid] = c1b[tid];
    for (int i = tid; i < 256; i += 288) skoffc[i] = g_koffc[i];
    for (int i = tid; i < 640; i += 288) skoffp[i] = g_koffp[i];
    __syncthreads();

    // prefetch conv2 B window 0 (hidden behind conv1)
    for (int i = tid; i < 4096; i += 288) {
        int row = i >> 6, n = i & 63;
        CP_ASYNC8(sptr(&sBf0[row * 65 + n]), &g_w2f[i]);
    }
    CP_COMMIT;

    // ---- conv1 + pool (exact fp32): one patch per item serves 4 ocs ----
    for (int i = tid; i < 2240; i += 288) {
        int og = i / 448, pos = i % 448;
        int ph = pos / 28, pw = pos % 28;
        int r0 = ph * 2, c0 = pw * 2;
        float patch[6][6];
#pragma unroll
        for (int pr = 0; pr < 6; pr++) {
            const float2* row = (const float2*)&sx1[(r0 + pr) * 60 + c0];
            float2 p0 = row[0], p1 = row[1], p2 = row[2];
            patch[pr][0] = p0.x; patch[pr][1] = p0.y;
            patch[pr][2] = p1.x; patch[pr][3] = p1.y;
            patch[pr][4] = p2.x; patch[pr][5] = p2.y;
        }
        int oc0 = og * 4;
#pragma unroll
        for (int o = 0; o < 4; o++) {
            const float* wp = &sw1[(oc0 + o) * 25];
            float a00 = 0, a01 = 0, a10 = 0, a11 = 0;
#pragma unroll
            for (int kr = 0; kr < 5; kr++)
#pragma unroll
                for (int kc = 0; kc < 5; kc++) {
                    float wv = wp[kr * 5 + kc];
                    a00 = fmaf(patch[kr][kc],         wv, a00);
                    a01 = fmaf(patch[kr][kc + 1],     wv, a01);
                    a10 = fmaf(patch[kr + 1][kc],     wv, a10);
                    a11 = fmaf(patch[kr + 1][kc + 1], wv, a11);
                }
            sxt[(oc0 + o) * 448 + pos] =
                f2tf(fmaxf(fmaxf(a00, a01), fmaxf(a10, a11)) + sb1[oc0 + o]);
        }
    }
    for (int i = 8960 + tid; i < 9292; i += 288) sxt[i] = 0u;
    __syncthreads();   // conv1 done; sx1 dead

    // prefetch window 1 into sBf1 (sx1 region now dead)
    for (int i = tid; i < 4096; i += 288) {
        int row = i >> 6, n = i & 63;
        CP_ASYNC8(sptr(&sBf1[row * 65 + n]), &g_w2f[4096 + i]);
    }
    CP_COMMIT;
    CP_WAIT(1);
    __syncthreads();   // window 0 visible

    // ---- conv2 via tf32 mma: M=288, N=56(50), K=512(500), double-buffered B ----
    float acc[2][7][4];
#pragma unroll
    for (int s = 0; s < 2; s++)
#pragma unroll
        for (int nt = 0; nt < 7; nt++)
#pragma unroll
            for (int q = 0; q < 4; q++) acc[s][nt][q] = 0.f;

    int pb[2][2];
#pragma unroll
    for (int s = 0; s < 2; s++) {
        int m0 = (warp * 2 + s) * 16 + g;
        pb[s][0] = (m0 / 24) * 28 + (m0 % 24);
        int m1 = m0 + 8;
        pb[s][1] = (m1 / 24) * 28 + (m1 % 24);
    }

    for (int win = 0; win < 4; win++) {
        uint2* sBf = (win & 1) ? sBf1 : sBf0;
#pragma unroll 4
        for (int wk = 0; wk < 16; wk++) {
            int2 ko = skoffc[(win * 16 + wk) * 4 + t];
            unsigned a[2][4];
#pragma unroll
            for (int s = 0; s < 2; s++) {
                a[s][0] = sxt[pb[s][0] + ko.x];
                a[s][1] = sxt[pb[s][1] + ko.x];
                a[s][2] = sxt[pb[s][0] + ko.y];
                a[s][3] = sxt[pb[s][1] + ko.y];
            }
#pragma unroll
            for (int nt = 0; nt < 7; nt++) {
                uint2 bb = sBf[(wk * 4 + t) * 65 + nt * 8 + g];
                mma8(acc[0][nt], a[0][0], a[0][1], a[0][2], a[0][3], bb.x, bb.y);
                mma8(acc[1][nt], a[1][0], a[1][1], a[1][2], a[1][3], bb.x, bb.y);
            }
        }
        __syncthreads();   // done reading this buffer
        if (win < 2) {
            for (int i = tid; i < 4096; i += 288) {
                int row = i >> 6, n = i & 63;
                CP_ASYNC8(sptr(&sBf[row * 65 + n]), &g_w2f[(win + 2) * 4096 + i]);
            }
            CP_COMMIT;
            CP_WAIT(1);
        } else {
            CP_WAIT(0);
        }
        __syncthreads();   // next buffer visible
    }

    // ---- writeout conv2 pre-pool (sconv aliases sxt/sBf0) + zero pcaps buffer ----
#pragma unroll
    for (int s = 0; s < 2; s++) {
        int m0 = (warp * 2 + s) * 16 + g;
#pragma unroll
        for (int nt = 0; nt < 7; nt++) {
            int n0 = nt * 8 + 2 * t;
            if (n0 < 50) {
                sconv[n0 * 288 + m0]     = acc[s][nt][0];
                sconv[n0 * 288 + m0 + 8] = acc[s][nt][2];
            }
            if (n0 + 1 < 50) {
                sconv[(n0 + 1) * 288 + m0]     = acc[s][nt][1];
                sconv[(n0 + 1) * 288 + m0 + 8] = acc[s][nt][3];
            }
        }
    }
    for (int i = tid; i < 8096; i += 288) sh2p[i] = 0u;
    __syncthreads();

    // ---- maxpool + bias -> tf32; padded smem + g_h2 ----
    for (int i = tid; i < 3600; i += 288) {
        int oc = i / 72, rem = i % 72, ph = rem / 12, pw = rem % 12;
        const float* base = &sconv[oc * 288 + ph * 48 + pw * 2];
        float m = fmaxf(fmaxf(base[0], base[1]), fmaxf(base[24], base[25])) + c2b[oc];
        unsigned r = f2tf(m);
        sh2p[oc * 160 + (ph + 2) * 16 + (pw + 2)] = r;
        g_h2[b * 3600 + i] = __uint_as_float(r);
    }
    __syncthreads();   // sconv dead from here; swc region free

    // ---- stage pcaps weights through smem: 4 chunks x 40kc (20KB), double-buffered ----
    for (int i = tid; i < 1280; i += 288)
        CP_ASYNC16(sptr(&swc[i]), &g_wpa[i]);
    CP_COMMIT;
    for (int i = tid; i < 1280; i += 288)
        CP_ASYNC16(sptr(&swc[1280 + i]), &g_wpa[1280 + i]);
    CP_COMMIT;

    // ---- pcaps via tf32 mma, 4 independent acc chains, smem-staged weights ----
    {
        int nt = warp;
        int p = nt * 8 + g;
        int pbase = (p / 12) * 16 + (p % 12);
        float pa4[4][4];
#pragma unroll
        for (int c = 0; c < 4; c++)
#pragma unroll
            for (int q = 0; q < 4; q++) pa4[c][q] = 0.f;

        for (int ch = 0; ch < 4; ch++) {
            if (ch < 3) { CP_WAIT(1); } else { CP_WAIT(0); }
            __syncthreads();
            const uint4* wbuf = &swc[(ch & 1) * 1280];
#pragma unroll 4
            for (int j = 0; j < 40; j++) {
                int kc = ch * 40 + j;
                uint4 aa = wbuf[j * 32 + lane];
                int2 ko = skoffp[kc * 4 + t];
                unsigned b0 = sh2p[ko.x + pbase];
                unsigned b1 = sh2p[ko.y + pbase];
                mma8(pa4[kc & 3], aa.x, aa.y, aa.z, aa.w, b0, b1);
            }
            __syncthreads();
            if (ch + 2 < 4) {
                for (int i = tid; i < 1280; i += 288)
                    CP_ASYNC16(sptr(&swc[(ch & 1) * 1280 + i]), &g_wpa[(ch + 2) * 1280 + i]);
                CP_COMMIT;
            }
        }
        float pa[4];
#pragma unroll
        for (int q = 0; q < 4; q++)
            pa[q] = (pa4[0][q] + pa4[1][q]) + (pa4[2][q] + pa4[3][q]);

        int oc0 = g;
        int n0 = nt * 8 + 2 * t;
        float bsA = pcb[oc0], bsB = pcb[oc0 + 8];
        sp[oc0 * 72 + n0]           = pa[0] + bsA;
        sp[oc0 * 72 + n0 + 1]       = pa[1] + bsA;
        sp[(oc0 + 8) * 72 + n0]     = pa[2] + bsB;
        sp[(oc0 + 8) * 72 + n0 + 1] = pa[3] + bsB;
    }
    __syncthreads();

    // ---- squash + priors + 3-iter routing: warps 0,1 ----
    if (warp < 2) {
        int k = warp;
        float pr[9];
#pragma unroll
        for (int j = 0; j < 9; j++) {
            int r = lane + 32 * j;
            int cw = r / 72, hw = r % 72;
            const float* pbp = sp + cw * 72 + hw;
            float u0 = pbp[0], u1 = pbp[288], u2 = pbp[576], u3 = pbp[864];
            float n2 = u0 * u0 + u1 * u1 + u2 * u2 + u3 * u3;
            float f = sqrtf(n2) / (1.f + n2);
            float4 w4 = *(const float4*)&rw[(k * 288 + r) * 4];
            pr[j] = f * (u0 * w4.x + u1 * w4.y + u2 * w4.z + u3 * w4.w);
        }
        float S = 0.f;
#pragma unroll
        for (int j = 0; j < 9; j++) S += pr[j];
#pragma unroll
        for (int o = 16; o; o >>= 1) S += __shfl_xor_sync(0xffffffffu, S, o);
        float s = S * (1.f / 288.f);
        float v = sq1(s);
        float vsum = v;
#pragma unroll
        for (int it = 0; it < 2; it++) {
            float m = -1e30f;
#pragma unroll
            for (int j = 0; j < 9; j++) m = fmaxf(m, pr[j] * vsum);
#pragma unroll
            for (int o = 16; o; o >>= 1) m = fmaxf(m, __shfl_xor_sync(0xffffffffu, m, o));
            float Z = 0.f, T = 0.f;
#pragma unroll
            for (int j = 0; j < 9; j++) {
                float e = __expf(pr[j] * vsum - m);
                Z += e;
                T = fmaf(e, pr[j], T);
            }
#pragma unroll
            for (int o = 16; o; o >>= 1) {
                Z += __shfl_xor_sync(0xffffffffu, Z, o);
                T += __shfl_xor_sync(0xffffffffu, T, o);
            }
            float s2 = T / Z;
            v = sq1(s2);
            vsum += v;
        }
        if (lane == 0) g_c[b * 2 + k] = v;
    }
}

// ---------------- fc1 split-K: M=2048, N=512(500), K=3616(3602), Ksplit=4 ----------------
__global__ __launch_bounds__(256) void fc1_mma_k() {
    __shared__ __align__(16) unsigned As[3][64 * 36];
    __shared__ __align__(16) uint2 Bsp[3][16 * 65 + 8];
    int m0 = blockIdx.y * 64, n0 = blockIdx.x * 64;
    int ks = blockIdx.z;
    int ktb = (113 * ks) >> 2;
    int kte = (113 * (ks + 1)) >> 2;
    int tid = threadIdx.x, warp = tid >> 5, lane = tid & 31, g = lane >> 2, t = lane & 3;
    int ws = warp & 3;
    int wn = (warp >> 2) * 32;
    int mA = tid & 63, kslA = (tid >> 6) * 8;
    int nB = tid & 63, kgB = tid >> 6;

    float acc[4][4];
#pragma unroll
    for (int nt = 0; nt < 4; nt++)
#pragma unroll
        for (int q = 0; q < 4; q++) acc[nt][q] = 0.f;

    auto stage = [&](int kt, int buf) {
        if (kt < 112) {
            const float* src = &g_h2[(m0 + mA) * 3600 + kt * 32 + kslA];
            unsigned d0 = sptr(&As[buf][mA * 36 + kslA]);
            CP_ASYNC16(d0, src);
            CP_ASYNC16(d0 + 16, src + 4);
        } else {
#pragma unroll
            for (int q = 0; q < 8; q++) {
                int k = 3584 + kslA + q;
                unsigned v = 0u;
                if (k < 3600) v = __float_as_uint(g_h2[(m0 + mA) * 3600 + k]);
                else if (k < 3602) v = f2tf(g_c[(m0 + mA) * 2 + (k - 3600)]);
                As[buf][mA * 36 + kslA + q] = v;
            }
        }
#pragma unroll
        for (int kk = 0; kk < 4; kk++)
            CP_ASYNC8(sptr(&Bsp[buf][(kgB * 4 + kk) * 65 + nB]),
                      &g_w1p[(((kt * 4 + kgB) * 4) + kk) * 512 + n0 + nB]);
        CP_COMMIT;
    };

    stage(ktb,     0);
    stage(ktb + 1, 1);
    stage(ktb + 2, 2);

    int buf = 0;
    for (int kt = ktb; kt < kte; kt++) {
        if (kt < kte - 2) { CP_WAIT(2); }
        else if (kt == kte - 2) { CP_WAIT(1); }
        else { CP_WAIT(0); }
        __syncthreads();
#pragma unroll
        for (int kc = 0; kc < 4; kc++) {
            unsigned a0 = As[buf][(ws * 16 + g) * 36 + kc * 8 + t];
            unsigned a1 = As[buf][(ws * 16 + g + 8) * 36 + kc * 8 + t];
            unsigned a2 = As[buf][(ws * 16 + g) * 36 + kc * 8 + t + 4];
            unsigned a3 = As[buf][(ws * 16 + g + 8) * 36 + kc * 8 + t + 4];
#pragma unroll
            for (int nt = 0; nt < 4; nt++) {
                uint2 bb = Bsp[buf][(kc * 4 + t) * 65 + wn + nt * 8 + g];
                mma8(acc[nt], a0, a1, a2, a3, bb.x, bb.y);
            }
        }
        __syncthreads();
        if (kt + 3 < kte) stage(kt + 3, buf);
        buf = (buf == 2) ? 0 : buf + 1;
    }

    float* dst = &g_fp[(size_t)ks * NB * 512];
    int mrow = m0 + ws * 16 + g;
#pragma unroll
    for (int nt = 0; nt < 4; nt++) {
        int n = n0 + wn + nt * 8 + 2 * t;
        dst[mrow * 512 + n]           = acc[nt][0];
        dst[mrow * 512 + n + 1]       = acc[nt][1];
        dst[(mrow + 8) * 512 + n]     = acc[nt][2];
        dst[(mrow + 8) * 512 + n + 1] = acc[nt][3];
    }
}

// ---------------- fused fc1-reduce + fc2: one warp per image ----------------
__global__ __launch_bounds__(256) void fc2_k(
    const float* __restrict__ y, const float* __restrict__ f1b,
    const float* __restrict__ w2, const float* __restrict__ b2, float* __restrict__ out) {
    int b = (blockIdx.x * blockDim.x + threadIdx.x) >> 5;
    int lane = threadIdx.x & 31;
    const float* w0 = w2;
    const float* w1 = w2 + 502;
    float a0 = 0.f, a1 = 0.f;
    for (int j = lane; j < 500; j += 32) {
        int o = b * 512 + j;
        float v = (g_fp[o] + g_fp[NB * 512 + o]) +
                  (g_fp[2 * NB * 512 + o] + g_fp[3 * NB * 512 + o]);
        v = fmaxf(v + f1b[j], 0.f);
        a0 = fmaf(v, w0[j], a0);
        a1 = fmaf(v, w1[j], a1);
    }
    if (lane == 0) {
        float y0 = y[b * 2], y1 = y[b * 2 + 1];
        a0 += w0[500] * y0 + w0[501] * y1 + b2[0];
        a1 += w1[500] * y0 + w1[501] * y1 + b2[1];
    }
#pragma unroll
    for (int off = 16; off; off >>= 1) {
        a0 += __shfl_xor_sync(0xffffffffu, a0, off);
        a1 += __shfl_xor_sync(0xffffffffu, a1, off);
    }
    if (lane == 0) {
        out[b * 2]     = a0;
        out[b * 2 + 1] = a1;
    }
}

// ---------------- launch ----------------
extern "C" void kernel_launch(void* const* d_in, const int* in_sizes, int n_in,
                              void* d_out, int out_size) {
    const float* x   = (const float*)d_in[0];
    const float* y   = (const float*)d_in[1];
    const float* c1w = (const float*)d_in[2];
    const float* c1b = (const float*)d_in[3];
    const float* c2w = (const float*)d_in[4];
    const float* c2b = (const float*)d_in[5];
    const float* pw  = (const float*)d_in[6];
    const float* pb  = (const float*)d_in[7];
    const float* rw  = (const float*)d_in[8];
    const float* f1w = (const float*)d_in[9];
    const float* f1b = (const float*)d_in[10];
    const float* f2w = (const float*)d_in[11];
    const float* f2b = (const float*)d_in[12];
    float* out = (float*)d_out;

    const int bb_smem = 108864;
    cudaFuncSetAttribute(backbone_k, cudaFuncAttributeMaxDynamicSharedMemorySize, bb_smem);

    prep_k<<<512, 256>>>(c2w, pw, f1w);
    backbone_k<<<NB, 288, bb_smem>>>(x, c1w, c1b, c2b, pb, rw);
    dim3 g4(8, 32, 4);
    fc1_mma_k<<<g4, 256>>>();
    fc2_k<<<NB / 8, 256>>>(y, f1b, f2w, f2b, out);
}